// round 14
// baseline (speedup 1.0000x reference)
#include <cuda_runtime.h>
#include <cuda_fp16.h>
#include <cstdint>

#define N_NODES 10000
#define N_EDGES 50000
#define IN_F    1433
#define OUT_F   256

#define K_PAD   1472           // K padded to multiple of 64
#define HSLOTS  736            // K_PAD/2 half2 slots per row
#define BK      64
#define N_KT    (K_PAD / BK)   // 23
#define M_PADR  10112          // 79 * 128
#define CAP     64             // per-node bucket capacity (max degree ~18)

// fused prep grid split: feat convert | W transpose | edge-bucket fill
#define PREP_FEAT_BLOCKS  N_NODES                 // [0, 10000)
#define PREP_W_BLOCKS     (46 * 8)                // [10000, 10368)
#define PREP_FILL_BLOCKS  196                     // [10368, 10564)
#define PREP_GRID         (PREP_FEAT_BLOCKS + PREP_W_BLOCKS + PREP_FILL_BLOCKS)

// -------- scratch (device globals; zero-initialized, no allocations) --------
__device__ __align__(16) __half2 g_feat16[(size_t)N_NODES * HSLOTS];
__device__ __align__(16) __half g_A[(size_t)M_PADR * K_PAD];
__device__ __align__(16) __half g_Wt[(size_t)OUT_F * K_PAD];
__device__ int g_cnt[N_NODES];     // zero-init; gather resets after use
__device__ int g_srcs[(size_t)N_NODES * CAP];

// ======================= helpers =======================
__device__ __forceinline__ uint32_t smem_u32(const void* p) {
    uint32_t a;
    asm("{ .reg .u64 t; cvta.to.shared.u64 t, %1; cvt.u32.u64 %0, t; }" : "=r"(a) : "l"(p));
    return a;
}
__device__ __forceinline__ void ldmx4(uint32_t* r, uint32_t addr) {
    asm volatile("ldmatrix.sync.aligned.m8n8.x4.shared.b16 {%0,%1,%2,%3}, [%4];"
                 : "=r"(r[0]), "=r"(r[1]), "=r"(r[2]), "=r"(r[3]) : "r"(addr));
}
__device__ __forceinline__ void mma_f16(float* d, const uint32_t* a, const uint32_t* b) {
    asm volatile(
        "mma.sync.aligned.m16n8k16.row.col.f32.f16.f16.f32 "
        "{%0,%1,%2,%3}, {%4,%5,%6,%7}, {%8,%9}, {%0,%1,%2,%3};"
        : "+f"(d[0]), "+f"(d[1]), "+f"(d[2]), "+f"(d[3])
        : "r"(a[0]), "r"(a[1]), "r"(a[2]), "r"(a[3]), "r"(b[0]), "r"(b[1]));
}
__device__ __forceinline__ void cp16(uint32_t dst, const void* src) {
    asm volatile("cp.async.cg.shared.global [%0], [%1], 16;" :: "r"(dst), "l"(src));
}
__device__ __forceinline__ void cp_commit() {
    asm volatile("cp.async.commit_group;" ::: "memory");
}
template <int N>
__device__ __forceinline__ void cp_wait() {
    asm volatile("cp.async.wait_group %0;" :: "n"(N) : "memory");
}

// ======================= edge decode =======================
__device__ __forceinline__ void read_edge(const void* edges, int e, int is64,
                                          int& dst, int& src) {
    if (is64) {
        const long long* e64 = (const long long*)edges;
        dst = (int)e64[2 * (size_t)e];
        src = (int)e64[2 * (size_t)e + 1];
    } else {
        const int* e32 = (const int*)edges;
        dst = e32[2 * e];
        src = e32[2 * e + 1];
    }
}

// -------- launch 1: fused prep (feat->fp16 | W->fp16^T | bucket fill) --------
__global__ __launch_bounds__(256)
void prep_kernel(const float* __restrict__ feat,
                 const float* __restrict__ W,
                 const void* __restrict__ edges) {
    int b = blockIdx.x;
    int tid = threadIdx.x;

    if (b < PREP_FEAT_BLOCKS) {
        int r = b;
        const float* __restrict__ frow = feat + (size_t)r * IN_F;
        __half2* drow = g_feat16 + (size_t)r * HSLOTS;
        #pragma unroll
        for (int j = 0; j < 3; j++) {
            int slot = tid + 256 * j;
            if (slot < HSLOTS) {
                int c = 2 * slot;
                float x = (c < IN_F) ? __ldg(frow + c) : 0.0f;
                float y = (c + 1 < IN_F) ? __ldg(frow + c + 1) : 0.0f;
                drow[slot] = __floats2half2_rn(x, y);
            }
        }
        return;
    }
    b -= PREP_FEAT_BLOCKS;

    if (b < PREP_W_BLOCKS) {
        // W transpose -> fp16; kblk = b % 46, nblk = b / 46
        __shared__ float tile[32][33];
        int k0 = (b % 46) * 32;
        int n0 = (b / 46) * 32;
        int tx = tid & 31, ty = tid >> 5;  // 32x8
        #pragma unroll
        for (int i = 0; i < 4; i++) {
            int k = k0 + ty + i * 8;
            tile[ty + i * 8][tx] = (k < IN_F) ? W[(size_t)k * OUT_F + n0 + tx] : 0.0f;
        }
        __syncthreads();
        #pragma unroll
        for (int i = 0; i < 4; i++) {
            int n = n0 + ty + i * 8;
            int k = k0 + tx;
            g_Wt[(size_t)n * K_PAD + k] = __float2half(tile[tx][ty + i * 8]);
        }
        return;
    }
    b -= PREP_W_BLOCKS;

    // bucket fill (per-block edge-width detect; g_cnt zeroed by prior gather/static init)
    {
        __shared__ int s_is64;
        if (tid == 0) {
            const int* e32 = (const int*)edges;
            int is64 = 1;
            for (int j = 0; j < 128; j++)
                if (e32[2 * j + 1] != 0) { is64 = 0; break; }
            s_is64 = is64;
        }
        __syncthreads();
        int e = b * 256 + tid;
        if (e >= N_EDGES) return;
        int dst, src;
        read_edge(edges, e, s_is64, dst, src);
        if (src < 0 || src >= N_NODES) return;
        if (dst < 0 || dst >= N_NODES) return;
        int slot = atomicAdd(&g_cnt[dst], 1);
        if (slot < CAP) g_srcs[(size_t)dst * CAP + slot] = src;
    }
}

// -------- launch 2: fused gather + noise + norm -> fp16 A (+ cnt reset) --------
__global__ __launch_bounds__(256)
void gather_kernel(const float* __restrict__ noise) {
    int node = blockIdx.x;
    int cnt = g_cnt[node];
    if (cnt > CAP) cnt = CAP;
    const int* bucket = g_srcs + (size_t)node * CAP;
    int tid = threadIdx.x;

    const float* __restrict__ nrow = noise + (size_t)node * IN_F;

    float2 acc[3];
    #pragma unroll
    for (int j = 0; j < 3; j++) {
        int slot = tid + 256 * j;
        float x = 0.0f, y = 0.0f;
        if (slot < HSLOTS) {
            int c = 2 * slot;
            if (c < IN_F) x = __ldg(nrow + c);
            if (c + 1 < IN_F) y = __ldg(nrow + c + 1);
        }
        acc[j] = make_float2(x, y);
    }

    int e = 0;
    for (; e + 2 <= cnt; e += 2) {
        int s0 = __ldg(bucket + e);
        int s1 = __ldg(bucket + e + 1);
        const __half2* __restrict__ f0 = g_feat16 + (size_t)s0 * HSLOTS;
        const __half2* __restrict__ f1 = g_feat16 + (size_t)s1 * HSLOTS;
        #pragma unroll
        for (int j = 0; j < 3; j++) {
            int slot = tid + 256 * j;
            if (slot < HSLOTS) {
                float2 a = __half22float2(__ldg(f0 + slot));
                float2 c = __half22float2(__ldg(f1 + slot));
                acc[j].x += a.x + c.x;
                acc[j].y += a.y + c.y;
            }
        }
    }
    if (e < cnt) {
        int s0 = __ldg(bucket + e);
        const __half2* __restrict__ f0 = g_feat16 + (size_t)s0 * HSLOTS;
        #pragma unroll
        for (int j = 0; j < 3; j++) {
            int slot = tid + 256 * j;
            if (slot < HSLOTS) {
                float2 a = __half22float2(__ldg(f0 + slot));
                acc[j].x += a.x;
                acc[j].y += a.y;
            }
        }
    }

    float ss = 0.0f;
    #pragma unroll
    for (int j = 0; j < 3; j++) ss += acc[j].x * acc[j].x + acc[j].y * acc[j].y;
    #pragma unroll
    for (int off = 16; off; off >>= 1)
        ss += __shfl_xor_sync(0xFFFFFFFFu, ss, off);
    __shared__ float sred[8];
    __shared__ float s_inv;
    int lane = tid & 31, w = tid >> 5;
    if (lane == 0) sred[w] = ss;
    __syncthreads();
    if (tid == 0) {
        float tot = 0.0f;
        #pragma unroll
        for (int i = 0; i < 8; i++) tot += sred[i];
        s_inv = 1.0f / fmaxf(sqrtf(tot), 1e-12f);
        g_cnt[node] = 0;   // reset for next replay (all reads of cnt happened pre-barrier)
    }
    __syncthreads();
    float inv = s_inv;

    __half2* arow = (__half2*)(g_A + (size_t)node * K_PAD);
    #pragma unroll
    for (int j = 0; j < 3; j++) {
        int slot = tid + 256 * j;
        if (slot < HSLOTS)
            arow[slot] = __floats2half2_rn(acc[j].x * inv, acc[j].y * inv);
    }
}

// -------- launch 3: GEMM fp16 mma, BM=128 BN=64 BK=64, 256 thr, 3-stage, reg-pipelined --------
// SMEM per stage: A 128x144 = 18432B | B 64x144 = 9216B -> 27648B; 3 stages = 82944B
#define ROWB    144
#define A_SZ    18432
#define STGSZ   27648
#define SMEM_SZ 82944

__global__ __launch_bounds__(256)
void gemm_mma_kernel(const float* __restrict__ bias, float* __restrict__ out) {
    extern __shared__ __align__(128) char smem[];
    uint32_t sb = smem_u32(smem);
    int tid = threadIdx.x;
    int lane = tid & 31, wid = tid >> 5;
    int warp_m = wid & 3;      // 4 warps along M: 32 rows each
    int warp_n = wid >> 2;     // 2 warps along N: 32 cols each
    int m0 = blockIdx.x * 128;
    int n0 = blockIdx.y * 64;

    float acc[2][4][4];
    #pragma unroll
    for (int t = 0; t < 2; t++)
        #pragma unroll
        for (int nt = 0; nt < 4; nt++)
            #pragma unroll
            for (int j = 0; j < 4; j++) acc[t][nt][j] = 0.0f;

    // fill one BK=64 stage (A 128 rows + B 64 rows): 1536 cp16, 6 per thread
    auto fill = [&](int stage, int k0) {
        uint32_t sbuf = sb + stage * STGSZ;
        #pragma unroll
        for (int i = 0; i < 6; i++) {
            int idx = tid + 256 * i;            // 0..1535
            int isB = (idx >= 1024);
            int cc = isB ? (idx - 1024) : idx;  // A: 0..1023, B: 0..511
            int row = cc >> 3, kc = cc & 7;
            const __half* g = isB ? g_Wt : g_A;
            int rbase = isB ? n0 : m0;
            uint32_t dst = sbuf + (isB ? A_SZ : 0) + row * ROWB + kc * 16;
            cp16(dst, g + (size_t)(rbase + row) * K_PAD + k0 + kc * 8);
        }
    };

    fill(0, 0);
    cp_commit();
    fill(1, BK);
    cp_commit();

    // fragment double-buffer
    uint32_t afr[2][2][4], bfr[2][2][4];
    int stage = 0;

    auto load_frags = [&](int buf, uint32_t bo, int kk) {
        #pragma unroll
        for (int t = 0; t < 2; t++) {
            uint32_t ro = (uint32_t)((warp_m * 32 + t * 16 + (lane & 15)) * ROWB
                                     + (kk + (lane >> 4) * 8) * 2);
            ldmx4(afr[buf][t], bo + ro);
        }
        #pragma unroll
        for (int u = 0; u < 2; u++) {
            uint32_t ro = (uint32_t)((warp_n * 32 + u * 16 + (lane & 15)) * ROWB
                                     + (kk + (lane >> 4) * 8) * 2);
            ldmx4(bfr[buf][u], bo + A_SZ + ro);
        }
    };
    auto do_mma = [&](int buf) {
        #pragma unroll
        for (int t = 0; t < 2; t++)
            #pragma unroll
            for (int u = 0; u < 2; u++)
                #pragma unroll
                for (int v = 0; v < 2; v++) {
                    int nt = u * 2 + v;
                    uint32_t bf[2] = { bfr[buf][u][v], bfr[buf][u][v + 2] };
                    mma_f16(acc[t][nt], afr[buf][t], bf);
                }
    };

    for (int kb = 0; kb < N_KT; kb++) {
        if (kb == N_KT - 1) cp_wait<0>(); else cp_wait<1>();
        __syncthreads();

        if (kb + 2 < N_KT) {
            fill((stage + 2) % 3, (kb + 2) * BK);
            cp_commit();
        }

        uint32_t bo = sb + stage * STGSZ;
        load_frags(0, bo, 0);
        #pragma unroll
        for (int ks = 0; ks < 4; ks++) {
            if (ks < 3) load_frags((ks + 1) & 1, bo, (ks + 1) * 16);
            do_mma(ks & 1);
        }
        __syncthreads();
        stage = (stage + 1) % 3;
    }

    // epilogue
    #pragma unroll
    for (int t = 0; t < 2; t++) {
        int gm = m0 + warp_m * 32 + t * 16 + (lane >> 2);
        #pragma unroll
        for (int nt = 0; nt < 4; nt++) {
            int col = n0 + warp_n * 32 + nt * 8 + 2 * (lane & 3);
            float2 b2 = *(const float2*)(bias + col);
            float* c = acc[t][nt];
            if (gm < N_NODES)
                *(float2*)(out + (size_t)gm * OUT_F + col) =
                    make_float2(c[0] + b2.x, c[1] + b2.y);
            if (gm + 8 < N_NODES)
                *(float2*)(out + (size_t)(gm + 8) * OUT_F + col) =
                    make_float2(c[2] + b2.x, c[3] + b2.y);
        }
    }
}

extern "C" void kernel_launch(void* const* d_in, const int* in_sizes, int n_in,
                              void* d_out, int out_size) {
    const float* feat   = (const float*)d_in[0];
    const void*  edges  = d_in[1];
    const float* weight = (const float*)d_in[2];
    const float* bias   = (const float*)d_in[3];
    const float* noise  = (const float*)d_in[4];
    float*       out    = (float*)d_out;

    (void)in_sizes; (void)n_in; (void)out_size;

    cudaFuncSetAttribute(gemm_mma_kernel, cudaFuncAttributeMaxDynamicSharedMemorySize, SMEM_SZ);

    prep_kernel<<<PREP_GRID, 256>>>(feat, weight, edges);
    gather_kernel<<<N_NODES, 256>>>(noise);
    gemm_mma_kernel<<<dim3(M_PADR / 128, OUT_F / 64), 256, SMEM_SZ>>>(bias, out);
}

// round 16
// speedup vs baseline: 1.0247x; 1.0247x over previous
#include <cuda_runtime.h>
#include <cuda_fp16.h>
#include <cstdint>

#define N_NODES 10000
#define N_EDGES 50000
#define IN_F    1433
#define OUT_F   256

#define K_PAD   1440           // K padded to multiple of 32
#define HSLOTS  720            // K_PAD/2 half2 slots per row
#define BK      32
#define N_KT    (K_PAD / BK)   // 45
#define M_PADR  10112          // 79 * 128
#define CAP     64             // per-node bucket capacity (max degree ~18)

// fused prep grid split: feat convert | W transpose | edge-bucket fill
#define PREP_FEAT_BLOCKS  N_NODES                 // [0, 10000)
#define PREP_W_BLOCKS     (45 * 8)                // [10000, 10360)
#define PREP_FILL_BLOCKS  196                     // [10360, 10556)
#define PREP_GRID         (PREP_FEAT_BLOCKS + PREP_W_BLOCKS + PREP_FILL_BLOCKS)

// -------- scratch (device globals; zero-initialized, no allocations) --------
__device__ __align__(16) __half2 g_feat16[(size_t)N_NODES * HSLOTS];
__device__ __align__(16) __half g_A[(size_t)M_PADR * K_PAD];
__device__ __align__(16) __half g_Wt[(size_t)OUT_F * K_PAD];
__device__ int g_cnt[N_NODES];     // zero-init; gather resets after use
__device__ int g_srcs[(size_t)N_NODES * CAP];

// ======================= helpers =======================
__device__ __forceinline__ uint32_t smem_u32(const void* p) {
    uint32_t a;
    asm("{ .reg .u64 t; cvta.to.shared.u64 t, %1; cvt.u32.u64 %0, t; }" : "=r"(a) : "l"(p));
    return a;
}
__device__ __forceinline__ void ldmx4(uint32_t* r, uint32_t addr) {
    asm volatile("ldmatrix.sync.aligned.m8n8.x4.shared.b16 {%0,%1,%2,%3}, [%4];"
                 : "=r"(r[0]), "=r"(r[1]), "=r"(r[2]), "=r"(r[3]) : "r"(addr));
}
__device__ __forceinline__ void mma_f16(float* d, const uint32_t* a, const uint32_t* b) {
    asm volatile(
        "mma.sync.aligned.m16n8k16.row.col.f32.f16.f16.f32 "
        "{%0,%1,%2,%3}, {%4,%5,%6,%7}, {%8,%9}, {%0,%1,%2,%3};"
        : "+f"(d[0]), "+f"(d[1]), "+f"(d[2]), "+f"(d[3])
        : "r"(a[0]), "r"(a[1]), "r"(a[2]), "r"(a[3]), "r"(b[0]), "r"(b[1]));
}
__device__ __forceinline__ void cp16(uint32_t dst, const void* src) {
    asm volatile("cp.async.cg.shared.global [%0], [%1], 16;" :: "r"(dst), "l"(src));
}
__device__ __forceinline__ void cp_commit() {
    asm volatile("cp.async.commit_group;" ::: "memory");
}
template <int N>
__device__ __forceinline__ void cp_wait() {
    asm volatile("cp.async.wait_group %0;" :: "n"(N) : "memory");
}

// ======================= edge decode =======================
__device__ __forceinline__ void read_edge(const void* edges, int e, int is64,
                                          int& dst, int& src) {
    if (is64) {
        const long long* e64 = (const long long*)edges;
        dst = (int)e64[2 * (size_t)e];
        src = (int)e64[2 * (size_t)e + 1];
    } else {
        const int* e32 = (const int*)edges;
        dst = e32[2 * e];
        src = e32[2 * e + 1];
    }
}

// -------- launch 1: fused prep (feat->fp16 | W->fp16^T | bucket fill) --------
__global__ __launch_bounds__(256)
void prep_kernel(const float* __restrict__ feat,
                 const float* __restrict__ W,
                 const void* __restrict__ edges) {
    int b = blockIdx.x;
    int tid = threadIdx.x;

    if (b < PREP_FEAT_BLOCKS) {
        // scalar-pair conversion (feat rows are only 4B-aligned: IN_F=1433 odd)
        int r = b;
        const float* __restrict__ frow = feat + (size_t)r * IN_F;
        __half2* drow = g_feat16 + (size_t)r * HSLOTS;
        #pragma unroll
        for (int j = 0; j < 3; j++) {
            int slot = tid + 256 * j;
            if (slot < HSLOTS) {
                int c = 2 * slot;
                float x = (c < IN_F) ? __ldg(frow + c) : 0.0f;
                float y = (c + 1 < IN_F) ? __ldg(frow + c + 1) : 0.0f;
                drow[slot] = __floats2half2_rn(x, y);
            }
        }
        return;
    }
    b -= PREP_FEAT_BLOCKS;

    if (b < PREP_W_BLOCKS) {
        // W transpose -> fp16; kblk = b % 45, nblk = b / 45
        __shared__ float tile[32][33];
        int k0 = (b % 45) * 32;
        int n0 = (b / 45) * 32;
        int tx = tid & 31, ty = tid >> 5;  // 32x8
        #pragma unroll
        for (int i = 0; i < 4; i++) {
            int k = k0 + ty + i * 8;
            tile[ty + i * 8][tx] = (k < IN_F) ? W[(size_t)k * OUT_F + n0 + tx] : 0.0f;
        }
        __syncthreads();
        #pragma unroll
        for (int i = 0; i < 4; i++) {
            int n = n0 + ty + i * 8;
            int k = k0 + tx;
            g_Wt[(size_t)n * K_PAD + k] = __float2half(tile[tx][ty + i * 8]);
        }
        return;
    }
    b -= PREP_W_BLOCKS;

    // bucket fill (per-block edge-width detect; g_cnt zeroed by prior gather/static init)
    {
        __shared__ int s_is64;
        if (tid == 0) {
            const int* e32 = (const int*)edges;
            int is64 = 1;
            for (int j = 0; j < 128; j++)
                if (e32[2 * j + 1] != 0) { is64 = 0; break; }
            s_is64 = is64;
        }
        __syncthreads();
        int e = b * 256 + tid;
        if (e >= N_EDGES) return;
        int dst, src;
        read_edge(edges, e, s_is64, dst, src);
        if (src < 0 || src >= N_NODES) return;
        if (dst < 0 || dst >= N_NODES) return;
        int slot = atomicAdd(&g_cnt[dst], 1);
        if (slot < CAP) g_srcs[(size_t)dst * CAP + slot] = src;
    }
}

// -------- launch 2: fused gather + noise + norm -> fp16 A (+ cnt reset) --------
__global__ __launch_bounds__(256)
void gather_kernel(const float* __restrict__ noise) {
    int node = blockIdx.x;
    int cnt = g_cnt[node];
    if (cnt > CAP) cnt = CAP;
    const int* bucket = g_srcs + (size_t)node * CAP;
    int tid = threadIdx.x;

    const float* __restrict__ nrow = noise + (size_t)node * IN_F;

    float2 acc[3];
    #pragma unroll
    for (int j = 0; j < 3; j++) {
        int slot = tid + 256 * j;
        float x = 0.0f, y = 0.0f;
        if (slot < HSLOTS) {
            int c = 2 * slot;
            if (c < IN_F) x = __ldg(nrow + c);
            if (c + 1 < IN_F) y = __ldg(nrow + c + 1);
        }
        acc[j] = make_float2(x, y);
    }

    int e = 0;
    for (; e + 2 <= cnt; e += 2) {
        int s0 = __ldg(bucket + e);
        int s1 = __ldg(bucket + e + 1);
        const __half2* __restrict__ f0 = g_feat16 + (size_t)s0 * HSLOTS;
        const __half2* __restrict__ f1 = g_feat16 + (size_t)s1 * HSLOTS;
        #pragma unroll
        for (int j = 0; j < 3; j++) {
            int slot = tid + 256 * j;
            if (slot < HSLOTS) {
                float2 a = __half22float2(__ldg(f0 + slot));
                float2 c = __half22float2(__ldg(f1 + slot));
                acc[j].x += a.x + c.x;
                acc[j].y += a.y + c.y;
            }
        }
    }
    if (e < cnt) {
        int s0 = __ldg(bucket + e);
        const __half2* __restrict__ f0 = g_feat16 + (size_t)s0 * HSLOTS;
        #pragma unroll
        for (int j = 0; j < 3; j++) {
            int slot = tid + 256 * j;
            if (slot < HSLOTS) {
                float2 a = __half22float2(__ldg(f0 + slot));
                acc[j].x += a.x;
                acc[j].y += a.y;
            }
        }
    }

    float ss = 0.0f;
    #pragma unroll
    for (int j = 0; j < 3; j++) ss += acc[j].x * acc[j].x + acc[j].y * acc[j].y;
    #pragma unroll
    for (int off = 16; off; off >>= 1)
        ss += __shfl_xor_sync(0xFFFFFFFFu, ss, off);
    __shared__ float sred[8];
    __shared__ float s_inv;
    int lane = tid & 31, w = tid >> 5;
    if (lane == 0) sred[w] = ss;
    __syncthreads();
    if (tid == 0) {
        float tot = 0.0f;
        #pragma unroll
        for (int i = 0; i < 8; i++) tot += sred[i];
        s_inv = 1.0f / fmaxf(sqrtf(tot), 1e-12f);
        g_cnt[node] = 0;   // reset for next replay (all reads of cnt happened pre-barrier)
    }
    __syncthreads();
    float inv = s_inv;

    __half2* arow = (__half2*)(g_A + (size_t)node * K_PAD);
    #pragma unroll
    for (int j = 0; j < 3; j++) {
        int slot = tid + 256 * j;
        if (slot < HSLOTS)
            arow[slot] = __floats2half2_rn(acc[j].x * inv, acc[j].y * inv);
    }
}

// -------- launch 3: GEMM fp16 mma, BM=128 BN=64 BK=32, 256 thr, 4-stage, reg-pipelined --------
// SMEM per stage: A 128x80 = 10240B | B 64x80 = 5120B -> 15360B; 4 stages = 61440B
#define ROWB    80
#define A_SZ    10240
#define STGSZ   15360
#define SMEM_SZ 61440

__global__ __launch_bounds__(256, 3)
void gemm_mma_kernel(const float* __restrict__ bias, float* __restrict__ out) {
    extern __shared__ __align__(128) char smem[];
    uint32_t sb = smem_u32(smem);
    int tid = threadIdx.x;
    int lane = tid & 31, wid = tid >> 5;
    int warp_m = wid & 3;      // 4 warps along M: 32 rows each
    int warp_n = wid >> 2;     // 2 warps along N: 32 cols each
    int m0 = blockIdx.x * 128;
    int n0 = blockIdx.y * 64;

    float acc[2][4][4];
    #pragma unroll
    for (int t = 0; t < 2; t++)
        #pragma unroll
        for (int nt = 0; nt < 4; nt++)
            #pragma unroll
            for (int j = 0; j < 4; j++) acc[t][nt][j] = 0.0f;

    // fill one BK=32 stage (A 128 rows + B 64 rows): 768 cp16, 3 per thread
    auto fill = [&](int stage, int k0) {
        uint32_t sbuf = sb + stage * STGSZ;
        #pragma unroll
        for (int i = 0; i < 3; i++) {
            int idx = tid + 256 * i;          // 0..767
            int isB = (idx >= 512);
            int cc = isB ? (idx - 512) : idx; // A: 0..511, B: 0..255
            int row = cc >> 2, kc = cc & 3;
            const __half* g = isB ? g_Wt : g_A;
            int rbase = isB ? n0 : m0;
            uint32_t dst = sbuf + (isB ? A_SZ : 0) + row * ROWB + kc * 16;
            cp16(dst, g + (size_t)(rbase + row) * K_PAD + k0 + kc * 8);
        }
    };

    fill(0, 0);
    cp_commit();
    fill(1, BK);
    cp_commit();
    fill(2, 2 * BK);
    cp_commit();

    uint32_t afr[2][2][4], bfr[2][2][4];
    int stage = 0;

    auto load_frags = [&](int buf, uint32_t bo, int kk) {
        #pragma unroll
        for (int t = 0; t < 2; t++) {
            uint32_t ro = (uint32_t)((warp_m * 32 + t * 16 + (lane & 15)) * ROWB
                                     + (kk + (lane >> 4) * 8) * 2);
            ldmx4(afr[buf][t], bo + ro);
        }
        #pragma unroll
        for (int u = 0; u < 2; u++) {
            uint32_t ro = (uint32_t)((warp_n * 32 + u * 16 + (lane & 15)) * ROWB
                                     + (kk + (lane >> 4) * 8) * 2);
            ldmx4(bfr[buf][u], bo + A_SZ + ro);
        }
    };
    auto do_mma = [&](int buf) {
        #pragma unroll
        for (int t = 0; t < 2; t++)
            #pragma unroll
            for (int u = 0; u < 2; u++)
                #pragma unroll
                for (int v = 0; v < 2; v++) {
                    int nt = u * 2 + v;
                    uint32_t bf[2] = { bfr[buf][u][v], bfr[buf][u][v + 2] };
                    mma_f16(acc[t][nt], afr[buf][t], bf);
                }
    };

    for (int kb = 0; kb < N_KT; kb++) {
        // allowed pending groups: 2 normally, 1 at N_KT-2, 0 at N_KT-1
        if (kb + 3 <= N_KT) cp_wait<2>();
        else if (kb + 2 == N_KT) cp_wait<1>();
        else cp_wait<0>();
        __syncthreads();

        if (kb + 3 < N_KT) {
            fill((stage + 3) & 3, (kb + 3) * BK);
            cp_commit();
        }

        uint32_t bo = sb + stage * STGSZ;
        load_frags(0, bo, 0);
        load_frags(1, bo, 16);
        do_mma(0);
        do_mma(1);
        __syncthreads();
        stage = (stage + 1) & 3;
    }

    // epilogue
    #pragma unroll
    for (int t = 0; t < 2; t++) {
        int gm = m0 + warp_m * 32 + t * 16 + (lane >> 2);
        #pragma unroll
        for (int nt = 0; nt < 4; nt++) {
            int col = n0 + warp_n * 32 + nt * 8 + 2 * (lane & 3);
            float2 b2 = *(const float2*)(bias + col);
            float* c = acc[t][nt];
            if (gm < N_NODES)
                *(float2*)(out + (size_t)gm * OUT_F + col) =
                    make_float2(c[0] + b2.x, c[1] + b2.y);
            if (gm + 8 < N_NODES)
                *(float2*)(out + (size_t)(gm + 8) * OUT_F + col) =
                    make_float2(c[2] + b2.x, c[3] + b2.y);
        }
    }
}

extern "C" void kernel_launch(void* const* d_in, const int* in_sizes, int n_in,
                              void* d_out, int out_size) {
    const float* feat   = (const float*)d_in[0];
    const void*  edges  = d_in[1];
    const float* weight = (const float*)d_in[2];
    const float* bias   = (const float*)d_in[3];
    const float* noise  = (const float*)d_in[4];
    float*       out    = (float*)d_out;

    (void)in_sizes; (void)n_in; (void)out_size;

    cudaFuncSetAttribute(gemm_mma_kernel, cudaFuncAttributeMaxDynamicSharedMemorySize, SMEM_SZ);

    prep_kernel<<<PREP_GRID, 256>>>(feat, weight, edges);
    gather_kernel<<<N_NODES, 256>>>(noise);
    gemm_mma_kernel<<<dim3(M_PADR / 128, OUT_F / 64), 256, SMEM_SZ>>>(bias, out);
}